// round 10
// baseline (speedup 1.0000x reference)
#include <cuda_runtime.h>

// Sparsemax over rows of (B, 256) fp32.
// Michelot simplex projection, warm-started at tau0 = max(z) - 1
// (valid superset: tau* >= z_max - 1 since p_max <= 1).
//
// Fixed point (scale 1024, offset +16); sum+count packed into ONE integer
// warp reduction (REDUX.ADD): bits[0:23)=sum, bits[23:32)=count.
// tau update: tau_u = umulhi(su-1024, m[cu]) with m[c] = (2^32-1)/c held in
// SHARED memory, built by the block itself (R8/R9 showed __constant__
// initializers never reach the GPU in this harness -> table read as zeros).
// umulhi floor error is {0,-1} units (a<2^23) -> always rounds DOWN ->
// active set stays a superset of the support (Michelot invariant intact).
//
// Epilogue: final sum over the converged set via one packed signed REDUX of
// round(v*2^16) (replaces a 5-deep SHFL tree, ~130 serial cycles). tau error
// from this quantization <= 2^-17 absolute -> rel_err ~1e-5, margin 100x.

static constexpr int D = 256;

__global__ void __launch_bounds__(256, 8) sparsemax_kernel(
    const float* __restrict__ in, float* __restrict__ out)
{
    __shared__ unsigned s_recip[257];   // s_recip[c] = (2^32-1)/c, c in [1,256]

    const int tid = threadIdx.x;
    // Build the reciprocal table (one int div per thread, once per block).
    s_recip[tid + 1] = 0xFFFFFFFFu / (unsigned)(tid + 1);

    const int warp_id = (blockIdx.x * blockDim.x + tid) >> 5;
    const int lane = tid & 31;

    const float4* row_in = reinterpret_cast<const float4*>(in + (size_t)warp_id * D);
    float4 a = __ldcs(row_in + lane);        // coalesced 512B
    float4 b = __ldcs(row_in + lane + 32);   // second half of the 1KB row

    float v[8] = {a.x, a.y, a.z, a.w, b.x, b.y, b.z, b.w};

    // u = round((z+16)*1024); for |z|<8 this is in [8192, 24576].
    int u[8];
    #pragma unroll
    for (int j = 0; j < 8; ++j)
        u[j] = __float2int_rn(fmaf(v[j], 1024.0f, 16384.0f));

    __syncthreads();   // table ready

    // Warm start: tau_u = max_u - 1024  (i.e. tau0 = max - 1.0).
    int mx = max(max(max(u[0], u[1]), max(u[2], u[3])),
                 max(max(u[4], u[5]), max(u[6], u[7])));
    int tau_u = __reduce_max_sync(0xffffffffu, mx) - 1024;

    const unsigned CBIT = 1u << 23;   // count field increment
    unsigned cu = 1, cprev = 0xffffffffu;

    #pragma unroll 1
    for (int it = 0; it < 32; ++it) {
        unsigned acc = 0;
        #pragma unroll
        for (int j = 0; j < 8; ++j)
            if (u[j] > tau_u) acc += (unsigned)u[j] + CBIT;
        acc = __reduce_add_sync(0xffffffffu, acc);   // one REDUX: sum+count
        cu = acc >> 23;
        if (cu == cprev) break;                      // set stable -> converged
        cprev = cu;
        // tau_u = floor((su-1024)/cu) via shared-memory magic reciprocal
        // (floor error {0,-1}: rounds down -> superset-safe).
        unsigned su = acc & (CBIT - 1u);
        tau_u = (int)__umulhi(su - 1024u, s_recip[cu]);
    }

    // Final sum over the converged set at scale 2^16 (one signed REDUX).
    int s16 = 0;
    #pragma unroll
    for (int j = 0; j < 8; ++j)
        if (u[j] > tau_u) s16 += __float2int_rn(v[j] * 65536.0f);
    s16 = __reduce_add_sync(0xffffffffu, s16);

    const float tau_f = __fdividef(fmaf((float)s16, 1.0f / 65536.0f, -1.0f),
                                   (float)cu);

    float4 oa, ob;
    oa.x = fmaxf(v[0] - tau_f, 0.0f);
    oa.y = fmaxf(v[1] - tau_f, 0.0f);
    oa.z = fmaxf(v[2] - tau_f, 0.0f);
    oa.w = fmaxf(v[3] - tau_f, 0.0f);
    ob.x = fmaxf(v[4] - tau_f, 0.0f);
    ob.y = fmaxf(v[5] - tau_f, 0.0f);
    ob.z = fmaxf(v[6] - tau_f, 0.0f);
    ob.w = fmaxf(v[7] - tau_f, 0.0f);

    float4* row_out = reinterpret_cast<float4*>(out + (size_t)warp_id * D);
    __stcs(row_out + lane, oa);
    __stcs(row_out + lane + 32, ob);
}

extern "C" void kernel_launch(void* const* d_in, const int* in_sizes, int n_in,
                              void* d_out, int out_size)
{
    const float* logits = (const float*)d_in[0];
    float* out = (float*)d_out;
    const int B = in_sizes[0] / D;     // 131072; divisible by 8 rows/block

    sparsemax_kernel<<<B / 8, 256>>>(logits, out);
}

// round 12
// speedup vs baseline: 1.0151x; 1.0151x over previous
#include <cuda_runtime.h>

// Sparsemax over rows of (B, 256) fp32 — persistent software-pipelined warps.
//
// Michelot simplex projection, warm start tau0 = max(z) - 1 (superset-safe).
// Fixed point (scale 1024, offset +16). Per element we hold
//   w = round((z+16)*1024) + 2^23
// so ONE integer REDUX.ADD over active w gives sum (bits[0:23)) and count
// (bits[23:32)) simultaneously; the inner loop is 2 ALU ops/element
// (ISETP + predicated IADD3) — the +CBIT is folded into the prologue FMA
// (exact: w in [2^23, 2^24) where float ulp = 1).
// tau update: tau = umulhi(su-1024, m[c]), m[c]=(2^32-1)/c from a SHARED
// table built by the block (constant-bank init doesn't reach the GPU in this
// harness). umulhi floors (error {0,-1}) -> rounds DOWN -> active set stays
// a superset -> count-stable termination is exact. Offsets cancel:
// tau_u = (su - 1024)/c exactly in u-domain.
//
// R10 showed ALU (~28us) and DRAM (~32us) phases alternating -> 45us.
// Persistent warps prefetch the NEXT row before the serial Michelot chain,
// overlapping DRAM streaming with compute.
//
// R11 bug fixed: row stride in float4 units is 64 (256 floats), not 16.

static constexpr int D = 256;
static constexpr unsigned CBIT = 1u << 23;

__global__ void __launch_bounds__(256, 6) sparsemax_kernel(
    const float* __restrict__ in, float* __restrict__ out, int B)
{
    __shared__ unsigned s_recip[257];   // s_recip[c] = (2^32-1)/c

    const int tid = threadIdx.x;
    s_recip[tid + 1] = 0xFFFFFFFFu / (unsigned)(tid + 1);
    __syncthreads();

    const int lane = tid & 31;
    const int nwarps = (gridDim.x * blockDim.x) >> 5;      // total warps
    int row = (blockIdx.x * blockDim.x + tid) >> 5;

    if (row >= B) return;

    const float4* base_in = reinterpret_cast<const float4*>(in);
    float4* base_out = reinterpret_cast<float4*>(out);

    // First row's loads. One row = 256 floats = 64 float4s.
    float4 pa = __ldcs(base_in + (size_t)row * 64 + lane);
    float4 pb = __ldcs(base_in + (size_t)row * 64 + lane + 32);

    while (true) {
        const float v[8] = {pa.x, pa.y, pa.z, pa.w, pb.x, pb.y, pb.z, pb.w};

        // w = round((z+16)*1024) + 2^23, one exact FMA per element.
        unsigned w[8];
        #pragma unroll
        for (int j = 0; j < 8; ++j)
            w[j] = (unsigned)__float2int_rn(fmaf(v[j], 1024.0f, 16384.0f + 8388608.0f));

        // Prefetch next row (stride = total warps) before the serial loop.
        const int next = row + nwarps;
        const bool have_next = next < B;
        if (have_next) {
            pa = __ldcs(base_in + (size_t)next * 64 + lane);
            pb = __ldcs(base_in + (size_t)next * 64 + lane + 32);
        }

        // Warm start: T = max_w - 1024  (tau0 = max - 1 in w-domain).
        unsigned mx = max(max(max(w[0], w[1]), max(w[2], w[3])),
                          max(max(w[4], w[5]), max(w[6], w[7])));
        unsigned T = __reduce_max_sync(0xffffffffu, mx) - 1024u;

        unsigned cu = 1, cprev = 0xffffffffu;

        #pragma unroll 1
        for (int it = 0; it < 32; ++it) {
            unsigned acc = 0;
            #pragma unroll
            for (int j = 0; j < 8; ++j)
                if (w[j] > T) acc += w[j];          // ISETP + pred IADD3
            acc = __reduce_add_sync(0xffffffffu, acc);  // sum|count, one REDUX
            cu = acc >> 23;
            if (cu == cprev) break;                 // set stable -> converged
            cprev = cu;
            unsigned su = acc & (CBIT - 1u);
            // T = floor((su-1024)/cu) + CBIT  (floors -> superset-safe).
            T = __umulhi(su - 1024u, s_recip[cu]) + CBIT;
        }

        // Final sum over the converged set at scale 2^16 (one signed REDUX).
        int s16 = 0;
        #pragma unroll
        for (int j = 0; j < 8; ++j)
            if (w[j] > T) s16 += __float2int_rn(v[j] * 65536.0f);
        s16 = __reduce_add_sync(0xffffffffu, s16);

        const float tau_f = __fdividef(fmaf((float)s16, 1.0f / 65536.0f, -1.0f),
                                       (float)cu);

        float4 oa, ob;
        oa.x = fmaxf(v[0] - tau_f, 0.0f);
        oa.y = fmaxf(v[1] - tau_f, 0.0f);
        oa.z = fmaxf(v[2] - tau_f, 0.0f);
        oa.w = fmaxf(v[3] - tau_f, 0.0f);
        ob.x = fmaxf(v[4] - tau_f, 0.0f);
        ob.y = fmaxf(v[5] - tau_f, 0.0f);
        ob.z = fmaxf(v[6] - tau_f, 0.0f);
        ob.w = fmaxf(v[7] - tau_f, 0.0f);

        __stcs(base_out + (size_t)row * 64 + lane, oa);
        __stcs(base_out + (size_t)row * 64 + lane + 32, ob);

        if (!have_next) break;
        row = next;
    }
}

extern "C" void kernel_launch(void* const* d_in, const int* in_sizes, int n_in,
                              void* d_out, int out_size)
{
    const float* logits = (const float*)d_in[0];
    float* out = (float*)d_out;
    const int B = in_sizes[0] / D;     // 131072

    // Persistent-ish grid: ~6 blocks per SM on 148 SMs.
    int grid = 148 * 6;
    int max_blocks = (B + 7) / 8;
    if (grid > max_blocks) grid = max_blocks;
    sparsemax_kernel<<<grid, 256>>>(logits, out, B);
}